// round 2
// baseline (speedup 1.0000x reference)
#include <cuda_runtime.h>
#include <cuda_bf16.h>
#include <math.h>

// R1: resubmission of R0 baseline — previous round failed with
// GPUAcquisitionTimeout (broker at capacity), no metrics were produced.

// ---------------- problem constants ----------------
#define BB    32
#define C_IN  4
#define IMG   256
#define PP    16
#define DD    1024
#define NH    16
#define HDIM  64
#define GRIDP 16
#define LL    256        // tokens
#define NL    6
#define MROWS (BB*LL)    // 8192
#define LN_EPS 1e-5f

// ---------------- scratch (device globals; no allocation allowed) ----------------
__device__ float g_h  [MROWS * DD];        // residual stream
__device__ float g_x1 [MROWS * DD];        // ln+mod output / patchified input
__device__ float g_x2 [MROWS * DD];        // attention output
__device__ float g_qkv[MROWS * 3 * DD];    // qkv
__device__ float g_big[MROWS * 4 * DD];    // mlp hidden
__device__ float g_te  [BB * DD];
__device__ float g_t1  [BB * DD];
__device__ float g_temb[BB * DD];
__device__ float g_cond[BB * DD];
__device__ float g_scond[BB * DD];
__device__ float g_mods[BB * 6 * DD];
__device__ float g_fin [BB * 2 * DD];

// ---------------- generic tiled fp32 GEMM with fused epilogues ----------------
// C[M,N] = epilogue(A[M,K] @ B[K,N] + bias[N])
// EPI 0: C = acc + bias
// EPI 1: C = silu(acc + bias)
// EPI 2: C += gate[b][gate_col + n] * (acc + bias)   (residual accumulate; b = row/256)
#define BM 128
#define BN 128
#define BK 16
#define TM 8
#define TN 8

template<int EPI>
__global__ __launch_bounds__(256) void gemm_kernel(
    const float* __restrict__ A, const float* __restrict__ Bw,
    const float* __restrict__ bias,
    const float* __restrict__ gate, int gate_col,
    float* __restrict__ C, int M, int N, int K)
{
    __shared__ float As[BK][BM];
    __shared__ float Bs[BK][BN];
    const int tid = threadIdx.x;
    const int row0 = blockIdx.y * BM;
    const int col0 = blockIdx.x * BN;
    const int tr = (tid >> 4) * TM;   // 0..120
    const int tc = (tid & 15) * TN;   // 0..120

    float acc[TM][TN];
#pragma unroll
    for (int i = 0; i < TM; i++)
#pragma unroll
        for (int j = 0; j < TN; j++) acc[i][j] = 0.f;

    for (int kt = 0; kt < K; kt += BK) {
        // load A tile (128 x 16) -> As[k][m] (transposed)
#pragma unroll
        for (int i = 0; i < 2; i++) {
            int l = tid * 2 + i;            // 0..511
            int m = l >> 2;
            int k4 = (l & 3) * 4;
            int gr = row0 + m;
            float4 v = make_float4(0.f, 0.f, 0.f, 0.f);
            if (gr < M) v = *(const float4*)(A + (size_t)gr * K + kt + k4);
            As[k4 + 0][m] = v.x; As[k4 + 1][m] = v.y;
            As[k4 + 2][m] = v.z; As[k4 + 3][m] = v.w;
        }
        // load B tile (16 x 128)
#pragma unroll
        for (int i = 0; i < 2; i++) {
            int l = tid * 2 + i;
            int k = l >> 5;
            int n4 = (l & 31) * 4;
            float4 v = *(const float4*)(Bw + (size_t)(kt + k) * N + col0 + n4);
            *(float4*)&Bs[k][n4] = v;
        }
        __syncthreads();
#pragma unroll
        for (int k = 0; k < BK; k++) {
            float af[TM], bf[TN];
#pragma unroll
            for (int i = 0; i < TM; i++) af[i] = As[k][tr + i];
#pragma unroll
            for (int j = 0; j < TN; j++) bf[j] = Bs[k][tc + j];
#pragma unroll
            for (int i = 0; i < TM; i++)
#pragma unroll
                for (int j = 0; j < TN; j++)
                    acc[i][j] += af[i] * bf[j];
        }
        __syncthreads();
    }

#pragma unroll
    for (int i = 0; i < TM; i++) {
        int gr = row0 + tr + i;
        if (gr >= M) break;
        int b = gr >> 8;   // row / 256 tokens
#pragma unroll
        for (int j = 0; j < TN; j++) {
            int gc = col0 + tc + j;
            float v = acc[i][j] + bias[gc];
            if (EPI == 1) v = v / (1.f + expf(-v));     // SiLU
            if (EPI == 2) {
                float g = gate[(size_t)b * (6 * DD) + gate_col + gc];
                C[(size_t)gr * N + gc] += g * v;
            } else {
                C[(size_t)gr * N + gc] = v;
            }
        }
    }
}

// ---------------- patchify: x[B,C,H,W] -> g_x1[B*L, 1024] ----------------
__global__ void patchify_kernel(const float* __restrict__ x, float* __restrict__ px)
{
    int r = blockIdx.x, tid = threadIdx.x;
    int b = r >> 8, l = r & 255, gy = l >> 4, gx = l & 15;
    int sd = tid * 4;
    int c = sd >> 8, py = (sd >> 4) & 15, pw = sd & 15;
    const float* src = x + (((size_t)(b * 4 + c) * 256 + gy * 16 + py) * 256 + gx * 16 + pw);
    *(float4*)(px + (size_t)r * DD + sd) = *(const float4*)src;
}

// ---------------- time embedding ----------------
__global__ void timeemb_kernel(const int* __restrict__ t, float* __restrict__ te)
{
    int b = blockIdx.x, i = threadIdx.x;   // i in 0..511
    double tb = (double)t[b];
    double ang = exp(-((double)i / 512.0) * 9.210340371976184);  // ln(10000)
    double a = tb * ang;
    te[b * DD + i]       = (float)sin(a);
    te[b * DD + 512 + i] = (float)cos(a);
}

// ---------------- cond = y_table[y] + temb ; scond = silu(cond) ----------------
__global__ void cond_kernel(const int* __restrict__ y, const float* __restrict__ ytab,
                            const float* __restrict__ temb,
                            float* __restrict__ cond, float* __restrict__ scond)
{
    int b = blockIdx.x, tid = threadIdx.x;
    int cls = y[b];
    float4 a = ((const float4*)(ytab + (size_t)cls * DD))[tid];
    float4 t = ((const float4*)(temb + (size_t)b * DD))[tid];
    float4 c = make_float4(a.x + t.x, a.y + t.y, a.z + t.z, a.w + t.w);
    ((float4*)(cond + (size_t)b * DD))[tid] = c;
    float4 s;
    s.x = c.x / (1.f + expf(-c.x));
    s.y = c.y / (1.f + expf(-c.y));
    s.z = c.z / (1.f + expf(-c.z));
    s.w = c.w / (1.f + expf(-c.w));
    ((float4*)(scond + (size_t)b * DD))[tid] = s;
}

// ---------------- fused LayerNorm + modulate ----------------
// out = ln(h_row) * (1 + mods[b][mod_col + c]) + mods[b][mod_col + 1024 + c]
__global__ void lnmod_kernel(const float* __restrict__ h, const float* __restrict__ mods,
                             int mod_col, float* __restrict__ out)
{
    int r = blockIdx.x, tid = threadIdx.x, b = r >> 8;
    __shared__ float rs[8], rss[8];
    __shared__ float smean, srstd;

    float4 v = ((const float4*)(h + (size_t)r * DD))[tid];
    float s  = v.x + v.y + v.z + v.w;
    float ss = v.x * v.x + v.y * v.y + v.z * v.z + v.w * v.w;
#pragma unroll
    for (int o = 16; o > 0; o >>= 1) {
        s  += __shfl_xor_sync(0xffffffffu, s,  o);
        ss += __shfl_xor_sync(0xffffffffu, ss, o);
    }
    int wid = tid >> 5, lane = tid & 31;
    if (lane == 0) { rs[wid] = s; rss[wid] = ss; }
    __syncthreads();
    if (tid == 0) {
        float S = 0.f, SS = 0.f;
        for (int i = 0; i < 8; i++) { S += rs[i]; SS += rss[i]; }
        float m = S * (1.f / DD);
        float var = SS * (1.f / DD) - m * m;
        smean = m; srstd = rsqrtf(var + LN_EPS);
    }
    __syncthreads();
    float m = smean, rstd = srstd;
    const float* mrow = mods + (size_t)b * (6 * DD) + mod_col;
    float4 sc = ((const float4*)mrow)[tid];
    float4 bb = ((const float4*)(mrow + DD))[tid];
    float4 o;
    o.x = (v.x - m) * rstd * (1.f + sc.x) + bb.x;
    o.y = (v.y - m) * rstd * (1.f + sc.y) + bb.y;
    o.z = (v.z - m) * rstd * (1.f + sc.z) + bb.z;
    o.w = (v.w - m) * rstd * (1.f + sc.w) + bb.w;
    ((float4*)(out + (size_t)r * DD))[tid] = o;
}

// ---------------- attention: one block per (batch, head) ----------------
#define KS_STRIDE 65
#define ATTN_SMEM_FLOATS (2 * 256 * KS_STRIDE + 8 * 64 + 8 * 256)
__global__ __launch_bounds__(256) void attn_kernel(
    const float* __restrict__ qkv, float* __restrict__ out)
{
    int bh = blockIdx.x;
    int b = bh >> 4, hh = bh & 15;
    extern __shared__ float sm[];
    float* Ks   = sm;                      // [256][65]
    float* Vs   = Ks + 256 * KS_STRIDE;    // [256][65]
    float* qbuf = Vs + 256 * KS_STRIDE;    // [8][64]
    float* pbuf = qbuf + 8 * 64;           // [8][256]

    int tid = threadIdx.x, wid = tid >> 5, lane = tid & 31;
    const float* base = qkv + (size_t)b * LL * (3 * DD) + hh * HDIM;

    // load K, V (coalesced float2 per lane, one row per warp)
    for (int j = wid; j < LL; j += 8) {
        const float* kro = base + (size_t)j * (3 * DD) + DD;
        const float* vro = kro + DD;
        float2 kv = *(const float2*)(kro + 2 * lane);
        Ks[j * KS_STRIDE + 2 * lane]     = kv.x;
        Ks[j * KS_STRIDE + 2 * lane + 1] = kv.y;
        float2 vv = *(const float2*)(vro + 2 * lane);
        Vs[j * KS_STRIDE + 2 * lane]     = vv.x;
        Vs[j * KS_STRIDE + 2 * lane + 1] = vv.y;
    }
    __syncthreads();

    float* qw = qbuf + wid * 64;
    float* pw = pbuf + wid * 256;

    for (int i = wid; i < LL; i += 8) {
        // stage q row in smem, then pull to registers
        const float* qro = base + (size_t)i * (3 * DD);
        float2 qv = *(const float2*)(qro + 2 * lane);
        qw[2 * lane] = qv.x; qw[2 * lane + 1] = qv.y;
        __syncwarp();
        float qreg[HDIM];
#pragma unroll
        for (int d = 0; d < HDIM; d++) qreg[d] = qw[d];

        // scores: lane covers j = jj*32 + lane
        float sreg[8];
#pragma unroll
        for (int jj = 0; jj < 8; jj++) {
            int j = jj * 32 + lane;
            float a = 0.f;
#pragma unroll
            for (int d = 0; d < HDIM; d++) a += qreg[d] * Ks[j * KS_STRIDE + d];
            sreg[jj] = a * 0.125f;   // HD^-0.5
        }
        // softmax over 256
        float mx = sreg[0];
#pragma unroll
        for (int jj = 1; jj < 8; jj++) mx = fmaxf(mx, sreg[jj]);
#pragma unroll
        for (int o = 16; o > 0; o >>= 1) mx = fmaxf(mx, __shfl_xor_sync(0xffffffffu, mx, o));
        float sum = 0.f;
#pragma unroll
        for (int jj = 0; jj < 8; jj++) { sreg[jj] = expf(sreg[jj] - mx); sum += sreg[jj]; }
#pragma unroll
        for (int o = 16; o > 0; o >>= 1) sum += __shfl_xor_sync(0xffffffffu, sum, o);
        float inv = 1.f / sum;
#pragma unroll
        for (int jj = 0; jj < 8; jj++) pw[jj * 32 + lane] = sreg[jj] * inv;
        __syncwarp();

        // out: lane owns d = lane, lane+32
        float o0 = 0.f, o1 = 0.f;
#pragma unroll 4
        for (int j = 0; j < LL; j++) {
            float p = pw[j];
            o0 += p * Vs[j * KS_STRIDE + lane];
            o1 += p * Vs[j * KS_STRIDE + lane + 32];
        }
        float* orow = out + (size_t)(b * LL + i) * DD + hh * HDIM;
        orow[lane]      = o0;
        orow[lane + 32] = o1;
        __syncwarp();
    }
}

// ---------------- final: LN + modulate + unpatchify ----------------
__global__ void final_kernel(const float* __restrict__ h, const float* __restrict__ fin,
                             float* __restrict__ out)
{
    int r = blockIdx.x, tid = threadIdx.x, b = r >> 8, l = r & 255;
    int gy = l >> 4, gx = l & 15;
    __shared__ float rs[8], rss[8];
    __shared__ float smean, srstd;

    float4 v = ((const float4*)(h + (size_t)r * DD))[tid];
    float s  = v.x + v.y + v.z + v.w;
    float ss = v.x * v.x + v.y * v.y + v.z * v.z + v.w * v.w;
#pragma unroll
    for (int o = 16; o > 0; o >>= 1) {
        s  += __shfl_xor_sync(0xffffffffu, s,  o);
        ss += __shfl_xor_sync(0xffffffffu, ss, o);
    }
    int wid = tid >> 5, lane = tid & 31;
    if (lane == 0) { rs[wid] = s; rss[wid] = ss; }
    __syncthreads();
    if (tid == 0) {
        float S = 0.f, SS = 0.f;
        for (int i = 0; i < 8; i++) { S += rs[i]; SS += rss[i]; }
        float m = S * (1.f / DD);
        float var = SS * (1.f / DD) - m * m;
        smean = m; srstd = rsqrtf(var + LN_EPS);
    }
    __syncthreads();
    float m = smean, rstd = srstd;
    float4 sc = ((const float4*)(fin + (size_t)b * (2 * DD)))[tid];
    float4 bb = ((const float4*)(fin + (size_t)b * (2 * DD) + DD))[tid];
    float4 o;
    o.x = (v.x - m) * rstd * (1.f + sc.x) + bb.x;
    o.y = (v.y - m) * rstd * (1.f + sc.y) + bb.y;
    o.z = (v.z - m) * rstd * (1.f + sc.z) + bb.z;
    o.w = (v.w - m) * rstd * (1.f + sc.w) + bb.w;
    int sd = tid * 4;
    int c = sd >> 8, py = (sd >> 4) & 15, pw = sd & 15;
    size_t oidx = (((size_t)(b * 4 + c) * 256 + gy * 16 + py) * 256 + gx * 16 + pw);
    *(float4*)(out + oidx) = o;
}

// ---------------- host side ----------------
static void gemm_launch(int epi, const float* A, const float* Bw, const float* bias,
                        const float* gate, int gate_col, float* C, int M, int N, int K)
{
    dim3 grid(N / BN, (M + BM - 1) / BM);
    dim3 block(256);
    switch (epi) {
        case 0: gemm_kernel<0><<<grid, block>>>(A, Bw, bias, gate, gate_col, C, M, N, K); break;
        case 1: gemm_kernel<1><<<grid, block>>>(A, Bw, bias, gate, gate_col, C, M, N, K); break;
        case 2: gemm_kernel<2><<<grid, block>>>(A, Bw, bias, gate, gate_col, C, M, N, K); break;
    }
}

extern "C" void kernel_launch(void* const* d_in, const int* in_sizes, int n_in,
                              void* d_out, int out_size)
{
    const float* x        = (const float*)d_in[0];
    const int*   y        = (const int*)  d_in[1];
    const int*   t        = (const int*)  d_in[2];
    const float* xw       = (const float*)d_in[3];
    const float* xb       = (const float*)d_in[4];
    // d_in[5] = pos_embed (unused by the faithful forward)
    const float* ytab     = (const float*)d_in[6];
    const float* tw1      = (const float*)d_in[7];
    const float* tb1      = (const float*)d_in[8];
    const float* tw2      = (const float*)d_in[9];
    const float* tb2      = (const float*)d_in[10];
    const float* qkvw     = (const float*)d_in[11];
    const float* qkvb     = (const float*)d_in[12];
    const float* projw    = (const float*)d_in[13];
    const float* projb    = (const float*)d_in[14];
    const float* mw1      = (const float*)d_in[15];
    const float* mb1      = (const float*)d_in[16];
    const float* mw2      = (const float*)d_in[17];
    const float* mb2      = (const float*)d_in[18];
    const float* condw    = (const float*)d_in[19];
    const float* condb    = (const float*)d_in[20];
    const float* finw     = (const float*)d_in[21];
    const float* finb     = (const float*)d_in[22];
    float* out = (float*)d_out;

    float *p_h, *p_x1, *p_x2, *p_qkv, *p_big;
    float *p_te, *p_t1, *p_temb, *p_cond, *p_scond, *p_mods, *p_fin;
    cudaGetSymbolAddress((void**)&p_h,    g_h);
    cudaGetSymbolAddress((void**)&p_x1,   g_x1);
    cudaGetSymbolAddress((void**)&p_x2,   g_x2);
    cudaGetSymbolAddress((void**)&p_qkv,  g_qkv);
    cudaGetSymbolAddress((void**)&p_big,  g_big);
    cudaGetSymbolAddress((void**)&p_te,   g_te);
    cudaGetSymbolAddress((void**)&p_t1,   g_t1);
    cudaGetSymbolAddress((void**)&p_temb, g_temb);
    cudaGetSymbolAddress((void**)&p_cond, g_cond);
    cudaGetSymbolAddress((void**)&p_scond,g_scond);
    cudaGetSymbolAddress((void**)&p_mods, g_mods);
    cudaGetSymbolAddress((void**)&p_fin,  g_fin);

    const int attn_smem = ATTN_SMEM_FLOATS * (int)sizeof(float);   // 143360
    cudaFuncSetAttribute((const void*)attn_kernel,
                         cudaFuncAttributeMaxDynamicSharedMemorySize, attn_smem);

    // conditioning path
    timeemb_kernel<<<BB, 512>>>(t, p_te);
    gemm_launch(1, p_te, tw1, tb1, nullptr, 0, p_t1, BB, DD, DD);        // silu(te@W1+b1)
    gemm_launch(0, p_t1, tw2, tb2, nullptr, 0, p_temb, BB, DD, DD);
    cond_kernel<<<BB, 256>>>(y, ytab, p_temb, p_cond, p_scond);

    // stem: patchify + embed
    patchify_kernel<<<MROWS, 256>>>(x, p_x1);
    gemm_launch(0, p_x1, xw, xb, nullptr, 0, p_h, MROWS, DD, DD);

    for (int l = 0; l < NL; l++) {
        const float* cw = condw + (size_t)l * DD * 6 * DD;
        const float* cb = condb + (size_t)l * 6 * DD;
        gemm_launch(0, p_scond, cw, cb, nullptr, 0, p_mods, BB, 6 * DD, DD);

        // attention branch
        lnmod_kernel<<<MROWS, 256>>>(p_h, p_mods, 0, p_x1);
        gemm_launch(0, p_x1, qkvw + (size_t)l * DD * 3 * DD, qkvb + (size_t)l * 3 * DD,
                    nullptr, 0, p_qkv, MROWS, 3 * DD, DD);
        attn_kernel<<<BB * NH, 256, attn_smem>>>(p_qkv, p_x2);
        gemm_launch(2, p_x2, projw + (size_t)l * DD * DD, projb + (size_t)l * DD,
                    p_mods, 2 * DD, p_h, MROWS, DD, DD);

        // mlp branch
        lnmod_kernel<<<MROWS, 256>>>(p_h, p_mods, 3 * DD, p_x1);
        gemm_launch(1, p_x1, mw1 + (size_t)l * DD * 4 * DD, mb1 + (size_t)l * 4 * DD,
                    nullptr, 0, p_big, MROWS, 4 * DD, DD);
        gemm_launch(2, p_big, mw2 + (size_t)l * 4 * DD * DD, mb2 + (size_t)l * DD,
                    p_mods, 5 * DD, p_h, MROWS, DD, 4 * DD);
    }

    // final modulation + unpatchify
    gemm_launch(0, p_cond, finw, finb, nullptr, 0, p_fin, BB, 2 * DD, DD);
    final_kernel<<<MROWS, 256>>>(p_h, p_fin, out);
}

// round 10
// speedup vs baseline: 2.1825x; 2.1825x over previous
#include <cuda_runtime.h>
#include <cuda_bf16.h>
#include <math.h>
#include <stdint.h>

// R10: identical resubmission of the TF32 tensor-core candidate — R3..R9 all
// failed at GPU acquisition (broker capacity), before compile/run.

// ---------------- problem constants ----------------
#define BB    32
#define DD    1024
#define NH    16
#define HDIM  64
#define LL    256
#define NL    6
#define MROWS (BB*LL)    // 8192
#define LN_EPS 1e-5f

// ---------------- scratch ----------------
__device__ float g_h  [MROWS * DD];
__device__ float g_x1 [MROWS * DD];
__device__ float g_x2 [MROWS * DD];
__device__ float g_qkv[MROWS * 3 * DD];
__device__ float g_big[MROWS * 4 * DD];
__device__ float g_te  [BB * DD];
__device__ float g_t1  [BB * DD];
__device__ float g_temb[BB * DD];
__device__ float g_cond[BB * DD];
__device__ float g_scond[BB * DD];
__device__ float g_mods[BB * 6 * DD];
__device__ float g_fin [BB * 2 * DD];

// ---------------- TF32 tensor GEMM ----------------
// C[M,N] = epilogue(A[M,K] @ B[K,N] + bias[N])
// EPI 0: store; EPI 1: silu; EPI 2: C += gate[row>>8][gate_col+n] * v
#define SA 36     // A smem stride: frag banks = (4*qr + qc) % 32, all distinct
#define SB 136    // B smem stride: frag banks = (8*k  + n ) % 32, all distinct

__device__ __forceinline__ uint32_t f2tf32(float x) {
    uint32_t r; asm("cvt.rna.tf32.f32 %0, %1;" : "=r"(r) : "f"(x)); return r;
}

template<int EPI>
__global__ __launch_bounds__(256) void tgemm_kernel(
    const float* __restrict__ A, const float* __restrict__ Bw,
    const float* __restrict__ bias,
    const float* __restrict__ gate, int gate_col,
    float* __restrict__ C, int M, int N, int K)
{
    __shared__ float As[128][SA];   // 18.0 KB
    __shared__ float Bs[32][SB];    // 17.4 KB
    const int tid  = threadIdx.x;
    const int lane = tid & 31, wid = tid >> 5;
    const int warpM = wid & 3, warpN = wid >> 2;   // 4 x 2 warps
    const int qr = lane >> 2, qc = lane & 3;
    const int row0 = blockIdx.y * 128, col0 = blockIdx.x * 128;

    float acc[2][8][4];
#pragma unroll
    for (int mi = 0; mi < 2; mi++)
#pragma unroll
        for (int ni = 0; ni < 8; ni++)
#pragma unroll
            for (int j = 0; j < 4; j++) acc[mi][ni][j] = 0.f;

    float4 pa[4], pb[4];

    auto loadG = [&](int kt) {
#pragma unroll
        for (int i = 0; i < 4; i++) {
            int f  = tid + i * 256;
            int r  = f >> 3, c = (f & 7) * 4;          // A: 128 rows x 8 float4
            int gr = row0 + r;
            pa[i] = (gr < M) ? *(const float4*)(A + (size_t)gr * K + kt + c)
                             : make_float4(0.f, 0.f, 0.f, 0.f);
            int rb = f >> 5, cb = (f & 31) * 4;        // B: 32 rows x 32 float4
            pb[i] = *(const float4*)(Bw + (size_t)(kt + rb) * N + col0 + cb);
        }
    };
    auto storeS = [&]() {
#pragma unroll
        for (int i = 0; i < 4; i++) {
            int f = tid + i * 256;
            int r = f >> 3, c = (f & 7) * 4;
            As[r][c + 0] = __uint_as_float(f2tf32(pa[i].x));
            As[r][c + 1] = __uint_as_float(f2tf32(pa[i].y));
            As[r][c + 2] = __uint_as_float(f2tf32(pa[i].z));
            As[r][c + 3] = __uint_as_float(f2tf32(pa[i].w));
            int rb = f >> 5, cb = (f & 31) * 4;
            Bs[rb][cb + 0] = __uint_as_float(f2tf32(pb[i].x));
            Bs[rb][cb + 1] = __uint_as_float(f2tf32(pb[i].y));
            Bs[rb][cb + 2] = __uint_as_float(f2tf32(pb[i].z));
            Bs[rb][cb + 3] = __uint_as_float(f2tf32(pb[i].w));
        }
    };
    auto compute = [&]() {
#pragma unroll
        for (int kk = 0; kk < 4; kk++) {
            const int k0 = kk * 8;
            uint32_t af[2][4];
#pragma unroll
            for (int mi = 0; mi < 2; mi++) {
                int r = warpM * 32 + mi * 16;
                af[mi][0] = __float_as_uint(As[r + qr    ][k0 + qc    ]);
                af[mi][1] = __float_as_uint(As[r + 8 + qr][k0 + qc    ]);
                af[mi][2] = __float_as_uint(As[r + qr    ][k0 + 4 + qc]);
                af[mi][3] = __float_as_uint(As[r + 8 + qr][k0 + 4 + qc]);
            }
            uint32_t bf[8][2];
#pragma unroll
            for (int ni = 0; ni < 8; ni++) {
                int c = warpN * 64 + ni * 8;
                bf[ni][0] = __float_as_uint(Bs[k0 + qc    ][c + qr]);
                bf[ni][1] = __float_as_uint(Bs[k0 + 4 + qc][c + qr]);
            }
#pragma unroll
            for (int mi = 0; mi < 2; mi++)
#pragma unroll
                for (int ni = 0; ni < 8; ni++)
                    asm volatile(
                        "mma.sync.aligned.m16n8k8.row.col.f32.tf32.tf32.f32 "
                        "{%0,%1,%2,%3}, {%4,%5,%6,%7}, {%8,%9}, {%0,%1,%2,%3};"
                        : "+f"(acc[mi][ni][0]), "+f"(acc[mi][ni][1]),
                          "+f"(acc[mi][ni][2]), "+f"(acc[mi][ni][3])
                        : "r"(af[mi][0]), "r"(af[mi][1]), "r"(af[mi][2]), "r"(af[mi][3]),
                          "r"(bf[ni][0]), "r"(bf[ni][1]));
        }
    };

    loadG(0);
    storeS();
    __syncthreads();
    for (int kt = 32; kt <= K; kt += 32) {
        if (kt < K) loadG(kt);
        compute();
        if (kt < K) {
            __syncthreads();
            storeS();
            __syncthreads();
        }
    }

    // epilogue
#pragma unroll
    for (int mi = 0; mi < 2; mi++) {
        int rbase = row0 + warpM * 32 + mi * 16 + qr;
#pragma unroll
        for (int half = 0; half < 2; half++) {
            int gr = rbase + half * 8;
            if (gr >= M) continue;
            int b = gr >> 8;
#pragma unroll
            for (int ni = 0; ni < 8; ni++) {
                int gc = col0 + warpN * 64 + ni * 8 + qc * 2;
                float v0 = acc[mi][ni][half * 2 + 0] + bias[gc];
                float v1 = acc[mi][ni][half * 2 + 1] + bias[gc + 1];
                if (EPI == 1) {
                    v0 = v0 / (1.f + expf(-v0));
                    v1 = v1 / (1.f + expf(-v1));
                }
                if (EPI == 2) {
                    float g0 = gate[(size_t)b * (6 * DD) + gate_col + gc];
                    float g1 = gate[(size_t)b * (6 * DD) + gate_col + gc + 1];
                    float2 old = *(float2*)(C + (size_t)gr * N + gc);
                    v0 = old.x + g0 * v0;
                    v1 = old.y + g1 * v1;
                }
                *(float2*)(C + (size_t)gr * N + gc) = make_float2(v0, v1);
            }
        }
    }
}

// ---------------- patchify ----------------
__global__ void patchify_kernel(const float* __restrict__ x, float* __restrict__ px)
{
    int r = blockIdx.x, tid = threadIdx.x;
    int b = r >> 8, l = r & 255, gy = l >> 4, gx = l & 15;
    int sd = tid * 4;
    int c = sd >> 8, py = (sd >> 4) & 15, pw = sd & 15;
    const float* src = x + (((size_t)(b * 4 + c) * 256 + gy * 16 + py) * 256 + gx * 16 + pw);
    *(float4*)(px + (size_t)r * DD + sd) = *(const float4*)src;
}

// ---------------- time embedding ----------------
__global__ void timeemb_kernel(const int* __restrict__ t, float* __restrict__ te)
{
    int b = blockIdx.x, i = threadIdx.x;   // 0..511
    double tb = (double)t[b];
    double ang = exp(-((double)i / 512.0) * 9.210340371976184);  // ln(10000)
    double a = tb * ang;
    te[b * DD + i]       = (float)sin(a);
    te[b * DD + 512 + i] = (float)cos(a);
}

// ---------------- cond / scond ----------------
__global__ void cond_kernel(const int* __restrict__ y, const float* __restrict__ ytab,
                            const float* __restrict__ temb,
                            float* __restrict__ cond, float* __restrict__ scond)
{
    int b = blockIdx.x, tid = threadIdx.x;
    int cls = y[b];
    float4 a = ((const float4*)(ytab + (size_t)cls * DD))[tid];
    float4 t = ((const float4*)(temb + (size_t)b * DD))[tid];
    float4 c = make_float4(a.x + t.x, a.y + t.y, a.z + t.z, a.w + t.w);
    ((float4*)(cond + (size_t)b * DD))[tid] = c;
    float4 s;
    s.x = c.x / (1.f + expf(-c.x));
    s.y = c.y / (1.f + expf(-c.y));
    s.z = c.z / (1.f + expf(-c.z));
    s.w = c.w / (1.f + expf(-c.w));
    ((float4*)(scond + (size_t)b * DD))[tid] = s;
}

// ---------------- fused LayerNorm + modulate ----------------
__global__ void lnmod_kernel(const float* __restrict__ h, const float* __restrict__ mods,
                             int mod_col, float* __restrict__ out)
{
    int r = blockIdx.x, tid = threadIdx.x, b = r >> 8;
    __shared__ float rs[8], rss[8];
    __shared__ float smean, srstd;

    float4 v = ((const float4*)(h + (size_t)r * DD))[tid];
    float s  = v.x + v.y + v.z + v.w;
    float ss = v.x * v.x + v.y * v.y + v.z * v.z + v.w * v.w;
#pragma unroll
    for (int o = 16; o > 0; o >>= 1) {
        s  += __shfl_xor_sync(0xffffffffu, s,  o);
        ss += __shfl_xor_sync(0xffffffffu, ss, o);
    }
    int wid = tid >> 5, lane = tid & 31;
    if (lane == 0) { rs[wid] = s; rss[wid] = ss; }
    __syncthreads();
    if (tid == 0) {
        float S = 0.f, SS = 0.f;
        for (int i = 0; i < 8; i++) { S += rs[i]; SS += rss[i]; }
        float m = S * (1.f / DD);
        float var = SS * (1.f / DD) - m * m;
        smean = m; srstd = rsqrtf(var + LN_EPS);
    }
    __syncthreads();
    float m = smean, rstd = srstd;
    const float* mrow = mods + (size_t)b * (6 * DD) + mod_col;
    float4 sc = ((const float4*)mrow)[tid];
    float4 bb = ((const float4*)(mrow + DD))[tid];
    float4 o;
    o.x = (v.x - m) * rstd * (1.f + sc.x) + bb.x;
    o.y = (v.y - m) * rstd * (1.f + sc.y) + bb.y;
    o.z = (v.z - m) * rstd * (1.f + sc.z) + bb.z;
    o.w = (v.w - m) * rstd * (1.f + sc.w) + bb.w;
    ((float4*)(out + (size_t)r * DD))[tid] = o;
}

// ---------------- attention (fp32, smem-resident K/V) ----------------
#define KS_STRIDE 65
#define ATTN_SMEM_FLOATS (2 * 256 * KS_STRIDE + 8 * 64 + 8 * 256)
__global__ __launch_bounds__(256) void attn_kernel(
    const float* __restrict__ qkv, float* __restrict__ out)
{
    int bh = blockIdx.x;
    int b = bh >> 4, hh = bh & 15;
    extern __shared__ float sm[];
    float* Ks   = sm;
    float* Vs   = Ks + 256 * KS_STRIDE;
    float* qbuf = Vs + 256 * KS_STRIDE;
    float* pbuf = qbuf + 8 * 64;

    int tid = threadIdx.x, wid = tid >> 5, lane = tid & 31;
    const float* base = qkv + (size_t)b * LL * (3 * DD) + hh * HDIM;

    for (int j = wid; j < LL; j += 8) {
        const float* kro = base + (size_t)j * (3 * DD) + DD;
        const float* vro = kro + DD;
        float2 kv = *(const float2*)(kro + 2 * lane);
        Ks[j * KS_STRIDE + 2 * lane]     = kv.x;
        Ks[j * KS_STRIDE + 2 * lane + 1] = kv.y;
        float2 vv = *(const float2*)(vro + 2 * lane);
        Vs[j * KS_STRIDE + 2 * lane]     = vv.x;
        Vs[j * KS_STRIDE + 2 * lane + 1] = vv.y;
    }
    __syncthreads();

    float* qw = qbuf + wid * 64;
    float* pw = pbuf + wid * 256;

    for (int i = wid; i < LL; i += 8) {
        const float* qro = base + (size_t)i * (3 * DD);
        float2 qv = *(const float2*)(qro + 2 * lane);
        qw[2 * lane] = qv.x; qw[2 * lane + 1] = qv.y;
        __syncwarp();
        float qreg[HDIM];
#pragma unroll
        for (int d = 0; d < HDIM; d++) qreg[d] = qw[d];

        float sreg[8];
#pragma unroll
        for (int jj = 0; jj < 8; jj++) {
            int j = jj * 32 + lane;
            float a = 0.f;
#pragma unroll
            for (int d = 0; d < HDIM; d++) a += qreg[d] * Ks[j * KS_STRIDE + d];
            sreg[jj] = a * 0.125f;
        }
        float mx = sreg[0];
#pragma unroll
        for (int jj = 1; jj < 8; jj++) mx = fmaxf(mx, sreg[jj]);
#pragma unroll
        for (int o = 16; o > 0; o >>= 1) mx = fmaxf(mx, __shfl_xor_sync(0xffffffffu, mx, o));
        float sum = 0.f;
#pragma unroll
        for (int jj = 0; jj < 8; jj++) { sreg[jj] = expf(sreg[jj] - mx); sum += sreg[jj]; }
#pragma unroll
        for (int o = 16; o > 0; o >>= 1) sum += __shfl_xor_sync(0xffffffffu, sum, o);
        float inv = 1.f / sum;
#pragma unroll
        for (int jj = 0; jj < 8; jj++) pw[jj * 32 + lane] = sreg[jj] * inv;
        __syncwarp();

        float o0 = 0.f, o1 = 0.f;
#pragma unroll 4
        for (int j = 0; j < LL; j++) {
            float p = pw[j];
            o0 += p * Vs[j * KS_STRIDE + lane];
            o1 += p * Vs[j * KS_STRIDE + lane + 32];
        }
        float* orow = out + (size_t)(b * LL + i) * DD + hh * HDIM;
        orow[lane]      = o0;
        orow[lane + 32] = o1;
        __syncwarp();
    }
}

// ---------------- final: LN + modulate + unpatchify ----------------
__global__ void final_kernel(const float* __restrict__ h, const float* __restrict__ fin,
                             float* __restrict__ out)
{
    int r = blockIdx.x, tid = threadIdx.x, b = r >> 8, l = r & 255;
    int gy = l >> 4, gx = l & 15;
    __shared__ float rs[8], rss[8];
    __shared__ float smean, srstd;

    float4 v = ((const float4*)(h + (size_t)r * DD))[tid];
    float s  = v.x + v.y + v.z + v.w;
    float ss = v.x * v.x + v.y * v.y + v.z * v.z + v.w * v.w;
#pragma unroll
    for (int o = 16; o > 0; o >>= 1) {
        s  += __shfl_xor_sync(0xffffffffu, s,  o);
        ss += __shfl_xor_sync(0xffffffffu, ss, o);
    }
    int wid = tid >> 5, lane = tid & 31;
    if (lane == 0) { rs[wid] = s; rss[wid] = ss; }
    __syncthreads();
    if (tid == 0) {
        float S = 0.f, SS = 0.f;
        for (int i = 0; i < 8; i++) { S += rs[i]; SS += rss[i]; }
        float m = S * (1.f / DD);
        float var = SS * (1.f / DD) - m * m;
        smean = m; srstd = rsqrtf(var + LN_EPS);
    }
    __syncthreads();
    float m = smean, rstd = srstd;
    float4 sc = ((const float4*)(fin + (size_t)b * (2 * DD)))[tid];
    float4 bb = ((const float4*)(fin + (size_t)b * (2 * DD) + DD))[tid];
    float4 o;
    o.x = (v.x - m) * rstd * (1.f + sc.x) + bb.x;
    o.y = (v.y - m) * rstd * (1.f + sc.y) + bb.y;
    o.z = (v.z - m) * rstd * (1.f + sc.z) + bb.z;
    o.w = (v.w - m) * rstd * (1.f + sc.w) + bb.w;
    int sd = tid * 4;
    int c = sd >> 8, py = (sd >> 4) & 15, pw = sd & 15;
    size_t oidx = (((size_t)(b * 4 + c) * 256 + gy * 16 + py) * 256 + gx * 16 + pw);
    *(float4*)(out + oidx) = o;
}

// ---------------- host side ----------------
static void gemm_launch(int epi, const float* A, const float* Bw, const float* bias,
                        const float* gate, int gate_col, float* C, int M, int N, int K)
{
    dim3 grid(N / 128, (M + 127) / 128);
    dim3 block(256);
    switch (epi) {
        case 0: tgemm_kernel<0><<<grid, block>>>(A, Bw, bias, gate, gate_col, C, M, N, K); break;
        case 1: tgemm_kernel<1><<<grid, block>>>(A, Bw, bias, gate, gate_col, C, M, N, K); break;
        case 2: tgemm_kernel<2><<<grid, block>>>(A, Bw, bias, gate, gate_col, C, M, N, K); break;
    }
}

extern "C" void kernel_launch(void* const* d_in, const int* in_sizes, int n_in,
                              void* d_out, int out_size)
{
    const float* x        = (const float*)d_in[0];
    const int*   y        = (const int*)  d_in[1];
    const int*   t        = (const int*)  d_in[2];
    const float* xw       = (const float*)d_in[3];
    const float* xb       = (const float*)d_in[4];
    // d_in[5] = pos_embed (unused by the faithful forward)
    const float* ytab     = (const float*)d_in[6];
    const float* tw1      = (const float*)d_in[7];
    const float* tb1      = (const float*)d_in[8];
    const float* tw2      = (const float*)d_in[9];
    const float* tb2      = (const float*)d_in[10];
    const float* qkvw     = (const float*)d_in[11];
    const float* qkvb     = (const float*)d_in[12];
    const float* projw    = (const float*)d_in[13];
    const float* projb    = (const float*)d_in[14];
    const float* mw1      = (const float*)d_in[15];
    const float* mb1      = (const float*)d_in[16];
    const float* mw2      = (const float*)d_in[17];
    const float* mb2      = (const float*)d_in[18];
    const float* condw    = (const float*)d_in[19];
    const float* condb    = (const float*)d_in[20];
    const float* finw     = (const float*)d_in[21];
    const float* finb     = (const float*)d_in[22];
    float* out = (float*)d_out;

    float *p_h, *p_x1, *p_x2, *p_qkv, *p_big;
    float *p_te, *p_t1, *p_temb, *p_cond, *p_scond, *p_mods, *p_fin;
    cudaGetSymbolAddress((void**)&p_h,    g_h);
    cudaGetSymbolAddress((void**)&p_x1,   g_x1);
    cudaGetSymbolAddress((void**)&p_x2,   g_x2);
    cudaGetSymbolAddress((void**)&p_qkv,  g_qkv);
    cudaGetSymbolAddress((void**)&p_big,  g_big);
    cudaGetSymbolAddress((void**)&p_te,   g_te);
    cudaGetSymbolAddress((void**)&p_t1,   g_t1);
    cudaGetSymbolAddress((void**)&p_temb, g_temb);
    cudaGetSymbolAddress((void**)&p_cond, g_cond);
    cudaGetSymbolAddress((void**)&p_scond,g_scond);
    cudaGetSymbolAddress((void**)&p_mods, g_mods);
    cudaGetSymbolAddress((void**)&p_fin,  g_fin);

    const int attn_smem = ATTN_SMEM_FLOATS * (int)sizeof(float);
    cudaFuncSetAttribute((const void*)attn_kernel,
                         cudaFuncAttributeMaxDynamicSharedMemorySize, attn_smem);

    // conditioning path
    timeemb_kernel<<<BB, 512>>>(t, p_te);
    gemm_launch(1, p_te, tw1, tb1, nullptr, 0, p_t1, BB, DD, DD);
    gemm_launch(0, p_t1, tw2, tb2, nullptr, 0, p_temb, BB, DD, DD);
    cond_kernel<<<BB, 256>>>(y, ytab, p_temb, p_cond, p_scond);

    // stem
    patchify_kernel<<<MROWS, 256>>>(x, p_x1);
    gemm_launch(0, p_x1, xw, xb, nullptr, 0, p_h, MROWS, DD, DD);

    for (int l = 0; l < NL; l++) {
        const float* cw = condw + (size_t)l * DD * 6 * DD;
        const float* cb = condb + (size_t)l * 6 * DD;
        gemm_launch(0, p_scond, cw, cb, nullptr, 0, p_mods, BB, 6 * DD, DD);

        lnmod_kernel<<<MROWS, 256>>>(p_h, p_mods, 0, p_x1);
        gemm_launch(0, p_x1, qkvw + (size_t)l * DD * 3 * DD, qkvb + (size_t)l * 3 * DD,
                    nullptr, 0, p_qkv, MROWS, 3 * DD, DD);
        attn_kernel<<<BB * NH, 256, attn_smem>>>(p_qkv, p_x2);
        gemm_launch(2, p_x2, projw + (size_t)l * DD * DD, projb + (size_t)l * DD,
                    p_mods, 2 * DD, p_h, MROWS, DD, DD);

        lnmod_kernel<<<MROWS, 256>>>(p_h, p_mods, 3 * DD, p_x1);
        gemm_launch(1, p_x1, mw1 + (size_t)l * DD * 4 * DD, mb1 + (size_t)l * 4 * DD,
                    nullptr, 0, p_big, MROWS, 4 * DD, DD);
        gemm_launch(2, p_big, mw2 + (size_t)l * 4 * DD * DD, mb2 + (size_t)l * DD,
                    p_mods, 5 * DD, p_h, MROWS, DD, 4 * DD);
    }

    gemm_launch(0, p_cond, finw, finb, nullptr, 0, p_fin, BB, 2 * DD, DD);
    final_kernel<<<MROWS, 256>>>(p_h, p_fin, out);
}